// round 15
// baseline (speedup 1.0000x reference)
#include <cuda_runtime.h>
#include <math.h>

#define D     256
#define N0    1500
#define N1    1200
#define CATC  600
#define W96   96
#define NPIX  (N0*W96)      /* 144000 */
#define HID   256
#define H2    128
#define SPAD  36
#define SZB   (128*SPAD)
#define DYNSM (4*SZB*4)     /* 2 bufs x (A+B) = 73728 B */

/* ---------------- device scratch ----------------------------------------- */
__device__ float    g_s0[D];
__device__ float    g_accP[90][D];
__device__ float    g_t[W96];
__device__ float    g_hs[W96];
__device__ float    g_hp[W96+1];
__device__ float    g_meanH;
__device__ float    g_W1t[512*256];     /* W1 [k][o] fp32 (u-gemm)          */
__device__ unsigned g_W1tf[256*512];    /* W1 [o][k] tf32 bits              */
__device__ float    g_x [N0*D];
__device__ float    g_m0[N0*D];
__device__ float    g_m1[N0*D];
__device__ float    g_u [N0*D];
__device__ float    g_c1[(size_t)NPIX*HID];  /* relu(conv1) [pix][o]        */
__device__ float    g_sum1[HID];
__device__ float    g_sq1[HID];
__device__ float    g_sum2[H2];
__device__ float    g_sq2[H2];
__device__ unsigned g_W2p[H2*D];        /* W2 [o][c] tf32 bits              */
__device__ float    g_al[D];
__device__ float    g_b2p[H2];

__device__ __forceinline__ float sigm(float v) { return 1.f/(1.f+expf(-v)); }
__device__ __forceinline__ unsigned f2tf(float f) {
    unsigned u; asm("cvt.rna.tf32.f32 %0, %1;" : "=r"(u) : "f"(f)); return u;
}
__device__ __forceinline__ void mma8(float c[4], unsigned a0, unsigned a1,
                                     unsigned a2, unsigned a3,
                                     unsigned b0, unsigned b1) {
    asm("mma.sync.aligned.m16n8k8.row.col.f32.tf32.tf32.f32 "
        "{%0,%1,%2,%3},{%4,%5,%6,%7},{%8,%9},{%0,%1,%2,%3};"
        : "+f"(c[0]),"+f"(c[1]),"+f"(c[2]),"+f"(c[3])
        : "r"(a0),"r"(a1),"r"(a2),"r"(a3),"r"(b0),"r"(b1));
}
__device__ __forceinline__ void cpa16(void* dst, const void* src) {
    unsigned d = (unsigned)__cvta_generic_to_shared(dst);
    asm volatile("cp.async.cg.shared.global [%0], [%1], 16;"
                 :: "r"(d), "l"(src) : "memory");
}
#define CP_COMMIT() asm volatile("cp.async.commit_group;" ::: "memory")
#define CP_WAIT0()  asm volatile("cp.async.wait_group 0;" ::: "memory")

/* ---------------- init: W transforms + row partials ----------------------- */
__global__ void k_init(const float* __restrict__ W1, const float* __restrict__ W2,
                       const float* __restrict__ z0, const float* __restrict__ z1) {
    int b = blockIdx.x, t = threadIdx.x;
    if (b < 512) {
        float v = W1[t*512 + b];
        g_W1t [b*256 + t] = v;
        g_W1tf[t*512 + b] = f2tf(v);
        if (b < H2) g_W2p[b*256 + t] = f2tf(W2[b*256 + t]);
        if (b == 511) {
            g_sum1[t]=0.f; g_sq1[t]=0.f;
            if (t < H2) { g_sum2[t]=0.f; g_sq2[t]=0.f; }
        }
    } else {
        int r = b - 512;
        const float* src = (r < 50) ? (z0 + r*30*D) : (z1 + (r-50)*30*D);
        float acc = 0.f;
        #pragma unroll 6
        for (int i=0;i<30;i++) acc += src[i*D + t];
        g_accP[r][t] = acc;
    }
}

/* ---------------- prep: 2 blocks; sorts hm + prefix sums ------------------ */
__global__ void k_prep(const float* __restrict__ z1,
                       const float* __restrict__ w1, const float* __restrict__ w2,
                       const float* __restrict__ w3, const float* __restrict__ w4,
                       const float* __restrict__ w5,
                       const int* __restrict__ cdrH, const int* __restrict__ cdrL,
                       const int* __restrict__ notH, const int* __restrict__ notL,
                       int nHc, int nLc, int nHn, int nLn) {
    __shared__ float y0[D];
    __shared__ float accS[D];
    __shared__ float av[W96];
    __shared__ float bv[CATC];
    __shared__ float red[256];
    __shared__ float hmv[W96];
    __shared__ float hsS[W96];
    int t = threadIdx.x;
    int row = t >> 1, jp = t & 1;

    if (blockIdx.x == 0) {
        {
            float a = 0.f;
            for (int r=0;r<50;r++) a += g_accP[r][t];
            y0[t] = a * (1.f/N0);
            float hA = 0.f;
            for (int r=50;r<70;r++) hA += g_accP[r][t];
            accS[t] = hA;
        }
        __syncthreads();
        {
            float a = 0.f;
            #pragma unroll
            for (int k=0;k<5;k++) { int cc=t+k-2; if (cc>=0 && cc<D) a += w1[k]*y0[cc]; }
            g_s0[t] = sigm(a);
        }

        float sH0;
        {
            float yh0=accS[0]*(1.f/CATC), yh1=accS[1]*(1.f/CATC), yh2=accS[2]*(1.f/CATC);
            sH0 = sigm(w2[2]*yh0 + w2[3]*yh1 + w2[4]*yh2);
        }
        if (t < nHc) av[t] = z1[cdrH[t]*D] * sH0;
        for (int j=t; j<nHn; j+=256) bv[j] = z1[notH[j]*D] * sH0;
        __syncthreads();
        float msum = 0.f;
        if (row < nHc) {
            float ai = av[row];
            for (int j=jp; j<nHn; j+=2) msum += fabsf(ai - bv[j]);
        }
        msum += __shfl_down_sync(0xffffffffu, msum, 1, 2);
        red[t] = (jp==0 && row<nHc) ? msum : 0.f;
        __syncthreads();
        for (int m=128;m>0;m>>=1){ if(t<m) red[t]+=red[t+m]; __syncthreads(); }
        float s  = red[0] / ((float)nHc*(float)nHn);
        float gH = sigm(w4[2] * s);
        float myhm = gH * msum / (float)nHn;
        if (jp==0 && row < nHc) { g_t[row] = myhm; hmv[row] = myhm; }
        if (t==0) g_meanH = gH * s;
        __syncthreads();

        if (t < nHc) {
            float v = hmv[t]; int r = 0;
            for (int j=0;j<nHc;j++) { float vj = hmv[j]; r += (vj < v) || (vj == v && j < t); }
            hsS[r] = v;
        }
        __syncthreads();
        if (t < nHc) g_hs[t] = hsS[t];
        if (t == 0) {
            float run = 0.f;
            for (int j=0;j<nHc;j++) { g_hp[j] = run; run += hsS[j]; }
            g_hp[nHc] = run;
        }
    } else {
        {
            float a = 0.f;
            for (int r=70;r<90;r++) a += g_accP[r][t];
            accS[t] = a;
        }
        __syncthreads();
        float sL0;
        {
            float yl0=accS[0]*(1.f/CATC), yl1=accS[1]*(1.f/CATC), yl2=accS[2]*(1.f/CATC);
            sL0 = sigm(w3[2]*yl0 + w3[3]*yl1 + w3[4]*yl2);
        }
        if (t < nLc) av[t] = z1[(CATC+cdrL[t])*D] * sL0;
        for (int j=t; j<nLn; j+=256) bv[j] = z1[(CATC+notL[j])*D] * sL0;
        __syncthreads();
        float msum = 0.f;
        if (row < nLc) {
            float ai = av[row];
            for (int j=jp; j<nLn; j+=2) msum += fabsf(ai - bv[j]);
        }
        msum += __shfl_down_sync(0xffffffffu, msum, 1, 2);
        red[t] = (jp==0 && row<nLc) ? msum : 0.f;
        __syncthreads();
        for (int m=128;m>0;m>>=1){ if(t<m) red[t]+=red[t+m]; __syncthreads(); }
        float gL = sigm(w5[2] * red[0] / ((float)nLc*(float)nLn));
        if (jp==0 && row < nLc) g_t[nHc + row] = gL * msum / (float)nLn;
    }
}

/* ---------------- per-h vectors via sorted-prefix m0 ----------------------- */
#define HB 5
__global__ __launch_bounds__(256,2) void k_pre2(const float* __restrict__ z0, int nHc) {
    __shared__ float xsall[HB][D];
    __shared__ float hs[W96];
    __shared__ float hp[W96+1];
    const int t = threadIdx.x;
    const int hbase = blockIdx.x * HB;
    if (t < nHc)      hs[t] = g_hs[t];
    if (t <= nHc)     hp[t] = g_hp[t];
    const float s0 = g_s0[t];
    const float mh = g_meanH;
    const float inv = 1.f / (float)nHc;
    __syncthreads();
    const float Ptot = hp[nHc];
    #pragma unroll
    for (int hh=0; hh<HB; hh++) {
        int h = hbase + hh;
        float x = z0[h*D + t] * s0;
        xsall[hh][t] = x;
        g_x [h*D + t] = x;
        int lo = 0, hi = nHc;
        while (lo < hi) { int m = (lo+hi) >> 1; if (hs[m] <= x) lo = m+1; else hi = m; }
        float m0 = (x * (float)(2*lo - nHc) - 2.f*hp[lo] + Ptot) * inv;
        g_m0[h*D + t] = m0;
        g_m1[h*D + t] = x * mh;
    }
    __syncthreads();
    float u[HB];
    #pragma unroll
    for (int hh=0;hh<HB;hh++) u[hh]=0.f;
    #pragma unroll 4
    for (int c=0;c<D;c++) {
        float wv = g_W1t[(256+c)*256 + t];
        #pragma unroll
        for (int hh=0;hh<HB;hh++) u[hh] = fmaf(wv, xsall[hh][c], u[hh]);
    }
    #pragma unroll
    for (int hh=0;hh<HB;hh++) g_u[(hbase+hh)*D + t] = u[hh];
}

/* ======================================================================== */
/* Merged tf32 GEMM1: 128 thr, warps 2x2, warp tile 64x64 (0.125 B/MAC).    */
/* ======================================================================== */
__global__ __launch_bounds__(128,2) void k_g1(const float* __restrict__ b1,
                                              int nHc, int nLc,
                                              int totH, int totL, int gridLx) {
    extern __shared__ unsigned dyn[];
    unsigned* As = dyn;
    unsigned* Bs = dyn + 2*SZB;
    __shared__ int   hrow[128];
    __shared__ int   pcol[128];
    __shared__ float tcol[128];

    const int tid = threadIdx.x;
    const int wid = tid >> 5, lane = tid & 31;
    const int wm = wid >> 1, wn = wid & 1;
    const int g = lane >> 2, tig = lane & 3;
    const int ob = blockIdx.y * 128;
    const bool isL = ((int)blockIdx.x < gridLx);

    float c[4][8][4];
    #pragma unroll
    for (int i=0;i<4;i++) for (int j=0;j<8;j++) for (int k=0;k<4;k++) c[i][j][k]=0.f;
    float4 br[8];

    const int sm = tid;                 /* one full 32-k row per thread */
    const int so = sm*SPAD;
    const unsigned* wsrc = g_W1tf + (size_t)(ob+sm)*512;

    if (isL) {
        const int pb = blockIdx.x * 128;
        {
            int pix = pb + tid;
            if (pix >= totL) pix = totL - 1;
            int h = pix / nLc, w = pix - h*nLc;
            hrow[tid] = h*D; pcol[tid] = h*W96 + nHc + w; tcol[tid] = g_t[nHc + w];
        }
        __syncthreads();
        const int hb = hrow[sm];
        const float tv = tcol[sm];
        const float* src0 = g_m0 + hb;
        const float* src1 = g_m1 + hb;

        #pragma unroll
        for (int q=0;q<8;q++) cpa16(&As[so + q*4], wsrc + q*4);
        CP_COMMIT();
        #pragma unroll
        for (int q=0;q<8;q++) br[q] = *(const float4*)(src0 + q*4);
        #pragma unroll
        for (int q=0;q<8;q++) {
            uint4 o4;
            o4.x=f2tf(fabsf(br[q].x-tv)); o4.y=f2tf(fabsf(br[q].y-tv));
            o4.z=f2tf(fabsf(br[q].z-tv)); o4.w=f2tf(fabsf(br[q].w-tv));
            *(uint4*)&Bs[so + q*4] = o4;
        }
        CP_WAIT0();
        __syncthreads();

        for (int kc=0; kc<16; kc++) {
            const int cur = kc & 1, nxt = cur ^ 1;
            if (kc < 15) {
                const int kn = kc + 1;
                const float* s = (kn < 8) ? (src0 + kn*32) : (src1 + (kn-8)*32);
                #pragma unroll
                for (int q=0;q<8;q++) cpa16(&As[nxt*SZB + so + q*4], wsrc + kn*32 + q*4);
                CP_COMMIT();
                #pragma unroll
                for (int q=0;q<8;q++) br[q] = *(const float4*)(s + q*4);
            }
            const unsigned* Ab = As + cur*SZB;
            const unsigned* Bb = Bs + cur*SZB;
            #pragma unroll
            for (int ks=0; ks<4; ks++) {
                const int kk = ks*8;
                unsigned af[4][4], bf[8][2];
                #pragma unroll
                for (int mt=0;mt<4;mt++) {
                    int rb = (wm*64 + mt*16 + g)*SPAD + kk + tig;
                    af[mt][0]=Ab[rb]; af[mt][1]=Ab[rb+8*SPAD];
                    af[mt][2]=Ab[rb+4]; af[mt][3]=Ab[rb+8*SPAD+4];
                }
                #pragma unroll
                for (int nt=0;nt<8;nt++) {
                    int cb = (wn*64 + nt*8 + g)*SPAD + kk + tig;
                    bf[nt][0]=Bb[cb]; bf[nt][1]=Bb[cb+4];
                }
                #pragma unroll
                for (int mt=0;mt<4;mt++)
                    #pragma unroll
                    for (int nt=0;nt<8;nt++)
                        mma8(c[mt][nt], af[mt][0],af[mt][1],af[mt][2],af[mt][3],
                             bf[nt][0], bf[nt][1]);
            }
            if (kc < 15) {
                #pragma unroll
                for (int q=0;q<8;q++) {
                    uint4 o4;
                    o4.x=f2tf(fabsf(br[q].x-tv)); o4.y=f2tf(fabsf(br[q].y-tv));
                    o4.z=f2tf(fabsf(br[q].z-tv)); o4.w=f2tf(fabsf(br[q].w-tv));
                    *(uint4*)&Bs[nxt*SZB + so + q*4] = o4;
                }
                CP_WAIT0();
            }
            __syncthreads();
        }

        #pragma unroll
        for (int mt=0;mt<4;mt++) {
            #pragma unroll
            for (int half=0; half<2; half++) {
                int o = ob + wm*64 + mt*16 + g + half*8;
                float bias = b1[o];
                float s = 0.f, q = 0.f;
                #pragma unroll
                for (int nt=0;nt<8;nt++) {
                    #pragma unroll
                    for (int cc=0;cc<2;cc++) {
                        int n = wn*64 + nt*8 + tig*2 + cc;
                        float r = fmaxf(c[mt][nt][half*2+cc] + bias, 0.f);
                        if (pb + n < totL) {
                            g_c1[(size_t)pcol[n]*256 + o] = r;
                            s += r; q += r*r;
                        }
                    }
                }
                s += __shfl_down_sync(0xffffffffu, s, 2, 4);
                s += __shfl_down_sync(0xffffffffu, s, 1, 4);
                q += __shfl_down_sync(0xffffffffu, q, 2, 4);
                q += __shfl_down_sync(0xffffffffu, q, 1, 4);
                if (tig == 0) { atomicAdd(&g_sum1[o], s); atomicAdd(&g_sq1[o], q); }
            }
        }
    } else {
        const int pb = (blockIdx.x - gridLx) * 128;
        {
            int pix = pb + tid;
            if (pix >= totH) pix = totH - 1;
            int h = pix / nHc, w = pix - h*nHc;
            hrow[tid] = h*D; pcol[tid] = h*W96 + w; tcol[tid] = g_t[w];
        }
        __syncthreads();
        const int hb = hrow[sm];
        const float tv = tcol[sm];
        const float* xsrc = g_x + hb;

        #pragma unroll
        for (int q=0;q<8;q++) cpa16(&As[so + q*4], wsrc + q*4);
        CP_COMMIT();
        #pragma unroll
        for (int q=0;q<8;q++) br[q] = *(const float4*)(xsrc + q*4);
        #pragma unroll
        for (int q=0;q<8;q++) {
            uint4 o4;
            o4.x=f2tf(fabsf(br[q].x-tv)); o4.y=f2tf(fabsf(br[q].y-tv));
            o4.z=f2tf(fabsf(br[q].z-tv)); o4.w=f2tf(fabsf(br[q].w-tv));
            *(uint4*)&Bs[so + q*4] = o4;
        }
        CP_WAIT0();
        __syncthreads();

        for (int kc=0; kc<8; kc++) {
            const int cur = kc & 1, nxt = cur ^ 1;
            if (kc < 7) {
                #pragma unroll
                for (int q=0;q<8;q++) cpa16(&As[nxt*SZB + so + q*4], wsrc + (kc+1)*32 + q*4);
                CP_COMMIT();
                #pragma unroll
                for (int q=0;q<8;q++) br[q] = *(const float4*)(xsrc + (kc+1)*32 + q*4);
            }
            const unsigned* Ab = As + cur*SZB;
            const unsigned* Bb = Bs + cur*SZB;
            #pragma unroll
            for (int ks=0; ks<4; ks++) {
                const int kk = ks*8;
                unsigned af[4][4], bf[8][2];
                #pragma unroll
                for (int mt=0;mt<4;mt++) {
                    int rb = (wm*64 + mt*16 + g)*SPAD + kk + tig;
                    af[mt][0]=Ab[rb]; af[mt][1]=Ab[rb+8*SPAD];
                    af[mt][2]=Ab[rb+4]; af[mt][3]=Ab[rb+8*SPAD+4];
                }
                #pragma unroll
                for (int nt=0;nt<8;nt++) {
                    int cb = (wn*64 + nt*8 + g)*SPAD + kk + tig;
                    bf[nt][0]=Bb[cb]; bf[nt][1]=Bb[cb+4];
                }
                #pragma unroll
                for (int mt=0;mt<4;mt++)
                    #pragma unroll
                    for (int nt=0;nt<8;nt++)
                        mma8(c[mt][nt], af[mt][0],af[mt][1],af[mt][2],af[mt][3],
                             bf[nt][0], bf[nt][1]);
            }
            if (kc < 7) {
                #pragma unroll
                for (int q=0;q<8;q++) {
                    uint4 o4;
                    o4.x=f2tf(fabsf(br[q].x-tv)); o4.y=f2tf(fabsf(br[q].y-tv));
                    o4.z=f2tf(fabsf(br[q].z-tv)); o4.w=f2tf(fabsf(br[q].w-tv));
                    *(uint4*)&Bs[nxt*SZB + so + q*4] = o4;
                }
                CP_WAIT0();
            }
            __syncthreads();
        }

        #pragma unroll
        for (int mt=0;mt<4;mt++) {
            #pragma unroll
            for (int half=0; half<2; half++) {
                int o = ob + wm*64 + mt*16 + g + half*8;
                float bias = b1[o];
                float s = 0.f, q = 0.f;
                #pragma unroll
                for (int nt=0;nt<8;nt++) {
                    #pragma unroll
                    for (int cc=0;cc<2;cc++) {
                        int n = wn*64 + nt*8 + tig*2 + cc;
                        float r = c[mt][nt][half*2+cc]
                                + g_u[hrow[n] + o] * tcol[n] + bias;
                        r = fmaxf(r, 0.f);
                        if (pb + n < totH) {
                            g_c1[(size_t)pcol[n]*256 + o] = r;
                            s += r; q += r*r;
                        }
                    }
                }
                s += __shfl_down_sync(0xffffffffu, s, 2, 4);
                s += __shfl_down_sync(0xffffffffu, s, 1, 4);
                q += __shfl_down_sync(0xffffffffu, q, 2, 4);
                q += __shfl_down_sync(0xffffffffu, q, 1, 4);
                if (tig == 0) { atomicAdd(&g_sum1[o], s); atomicAdd(&g_sq1[o], q); }
            }
        }
    }
}

/* ---------------- fold: BN1 alpha/beta + folded bias only ------------------ */
__global__ void k_fold(const float* __restrict__ W2, const float* __restrict__ b2,
                       const float* __restrict__ g1, const float* __restrict__ bb1) {
    __shared__ float be[D];
    int t = threadIdx.x;
    float mean = g_sum1[t] * (1.f/NPIX);
    float var  = g_sq1[t]  * (1.f/NPIX) - mean*mean;
    float a    = g1[t] * rsqrtf(var + 1e-5f);
    g_al[t] = a;
    be[t] = bb1[t] - mean*a;
    __syncthreads();
    if (t < H2) {
        float s = b2[t];
        for (int c=0;c<D;c++) s += W2[t*D + c] * be[c];
        g_b2p[t] = s;
    }
}

/* ======================================================================== */
/* tf32 GEMM2: 128 thr, warps 2x2, warp tile 64x64. alpha in B-convert.     */
/* ======================================================================== */
__global__ __launch_bounds__(128,2) void k_gemm2(float* __restrict__ out) {
    extern __shared__ unsigned dyn[];
    unsigned* As = dyn;
    unsigned* Bs = dyn + 2*SZB;
    __shared__ float alS[D];

    const int tid = threadIdx.x;
    const int wid = tid >> 5, lane = tid & 31;
    const int wm = wid >> 1, wn = wid & 1;
    const int g = lane >> 2, tig = lane & 3;
    const int pb = blockIdx.x * 128;

    const int sm = tid;
    const int so = sm*SPAD;
    const unsigned* wsrc = g_W2p + sm*256;
    const float*    bsrc = g_c1 + (size_t)(pb+sm)*256;

    alS[tid] = g_al[tid];
    alS[tid+128] = g_al[tid+128];
    __syncthreads();

    float c[4][8][4];
    #pragma unroll
    for (int i=0;i<4;i++) for (int j=0;j<8;j++) for (int k=0;k<4;k++) c[i][j][k]=0.f;
    float4 br[8];

    #pragma unroll
    for (int q=0;q<8;q++) cpa16(&As[so + q*4], wsrc + q*4);
    CP_COMMIT();
    #pragma unroll
    for (int q=0;q<8;q++) br[q] = *(const float4*)(bsrc + q*4);
    #pragma unroll
    for (int q=0;q<8;q++) {
        int ch = q*4;
        uint4 o4;
        o4.x=f2tf(br[q].x*alS[ch]);   o4.y=f2tf(br[q].y*alS[ch+1]);
        o4.z=f2tf(br[q].z*alS[ch+2]); o4.w=f2tf(br[q].w*alS[ch+3]);
        *(uint4*)&Bs[so + q*4] = o4;
    }
    CP_WAIT0();
    __syncthreads();

    for (int kc=0; kc<8; kc++) {
        const int cur = kc & 1, nxt = cur ^ 1;
        if (kc < 7) {
            #pragma unroll
            for (int q=0;q<8;q++) cpa16(&As[nxt*SZB + so + q*4], wsrc + (kc+1)*32 + q*4);
            CP_COMMIT();
            #pragma unroll
            for (int q=0;q<8;q++) br[q] = *(const float4*)(bsrc + (kc+1)*32 + q*4);
        }
        const unsigned* Ab = As + cur*SZB;
        const unsigned* Bb = Bs + cur*SZB;
        #pragma unroll
        for (int ks=0; ks<4; ks++) {
            const int kk = ks*8;
            unsigned af[4][4], bf[8][2];
            #pragma unroll
            for (int mt=0;mt<4;mt++) {
                int rb = (wm*64 + mt*16 + g)*SPAD + kk + tig;
                af[mt][0]=Ab[rb]; af[mt][1]=Ab[rb+8*SPAD];
                af[mt][2]=Ab[rb+4]; af[mt][3]=Ab[rb+8*SPAD+4];
            }
            #pragma unroll
            for (int nt=0;nt<8;nt++) {
                int cb = (wn*64 + nt*8 + g)*SPAD + kk + tig;
                bf[nt][0]=Bb[cb]; bf[nt][1]=Bb[cb+4];
            }
            #pragma unroll
            for (int mt=0;mt<4;mt++)
                #pragma unroll
                for (int nt=0;nt<8;nt++)
                    mma8(c[mt][nt], af[mt][0],af[mt][1],af[mt][2],af[mt][3],
                         bf[nt][0], bf[nt][1]);
        }
        if (kc < 7) {
            #pragma unroll
            for (int q=0;q<8;q++) {
                int ch = (kc+1)*32 + q*4;
                uint4 o4;
                o4.x=f2tf(br[q].x*alS[ch]);   o4.y=f2tf(br[q].y*alS[ch+1]);
                o4.z=f2tf(br[q].z*alS[ch+2]); o4.w=f2tf(br[q].w*alS[ch+3]);
                *(uint4*)&Bs[nxt*SZB + so + q*4] = o4;
            }
            CP_WAIT0();
        }
        __syncthreads();
    }

    #pragma unroll
    for (int mt=0;mt<4;mt++) {
        #pragma unroll
        for (int half=0; half<2; half++) {
            int o = wm*64 + mt*16 + g + half*8;
            float bias = g_b2p[o];
            float s = 0.f, q = 0.f;
            #pragma unroll
            for (int nt=0;nt<8;nt++) {
                int n = pb + wn*64 + nt*8 + tig*2;
                float r0 = fmaxf(c[mt][nt][half*2+0] + bias, 0.f);
                float r1 = fmaxf(c[mt][nt][half*2+1] + bias, 0.f);
                *(float2*)&out[(size_t)o*NPIX + n] = make_float2(r0, r1);
                s += r0 + r1; q += r0*r0 + r1*r1;
            }
            s += __shfl_down_sync(0xffffffffu, s, 2, 4);
            s += __shfl_down_sync(0xffffffffu, s, 1, 4);
            q += __shfl_down_sync(0xffffffffu, q, 2, 4);
            q += __shfl_down_sync(0xffffffffu, q, 1, 4);
            if (tig == 0) { atomicAdd(&g_sum2[o], s); atomicAdd(&g_sq2[o], q); }
        }
    }
}

/* ---------------- final BN2 affine in place (a2/be2 inline) ---------------- */
__global__ void k_final(float* __restrict__ out,
                        const float* __restrict__ g2, const float* __restrict__ bb2) {
    size_t idx = (size_t)blockIdx.x*256 + threadIdx.x;
    size_t i4  = idx * 4;
    int c = (int)(i4 / NPIX);
    float mean = g_sum2[c]*(1.f/NPIX);
    float var  = g_sq2[c]*(1.f/NPIX) - mean*mean;
    float a    = g2[c]*rsqrtf(var + 1e-5f);
    float b    = bb2[c] - mean*a;
    float4 v = *(float4*)(out + i4);
    v.x = fmaf(a, v.x, b); v.y = fmaf(a, v.y, b);
    v.z = fmaf(a, v.z, b); v.w = fmaf(a, v.w, b);
    *(float4*)(out + i4) = v;
}

/* ---------------- launch -------------------------------------------------- */
extern "C" void kernel_launch(void* const* d_in, const int* in_sizes, int n_in,
                              void* d_out, int out_size) {
    const float* z0  = (const float*)d_in[0];
    const float* z1  = (const float*)d_in[1];
    const float* w1  = (const float*)d_in[2];
    const float* w2  = (const float*)d_in[3];
    const float* w3  = (const float*)d_in[4];
    const float* w4  = (const float*)d_in[5];
    const float* w5  = (const float*)d_in[6];
    const float* W1  = (const float*)d_in[7];
    const float* b1  = (const float*)d_in[8];
    const float* g1  = (const float*)d_in[9];
    const float* bb1 = (const float*)d_in[10];
    const float* W2  = (const float*)d_in[11];
    const float* b2  = (const float*)d_in[12];
    const float* g2  = (const float*)d_in[13];
    const float* bb2 = (const float*)d_in[14];
    const int* cdrH = (const int*)d_in[16];
    const int* cdrL = (const int*)d_in[17];
    const int* notH = (const int*)d_in[18];
    const int* notL = (const int*)d_in[19];
    int nHc = in_sizes[16], nLc = in_sizes[17];
    int nHn = in_sizes[18], nLn = in_sizes[19];
    float* out = (float*)d_out;

    cudaFuncSetAttribute(k_g1,    cudaFuncAttributeMaxDynamicSharedMemorySize, DYNSM);
    cudaFuncSetAttribute(k_gemm2, cudaFuncAttributeMaxDynamicSharedMemorySize, DYNSM);

    k_init  <<<602, 256>>>(W1, W2, z0, z1);                   /* launch 1 */
    k_prep  <<<2, 256>>>(z1, w1, w2, w3, w4, w5, cdrH, cdrL, notH, notL,
                         nHc, nLc, nHn, nLn);                 /* launch 2 */
    k_pre2  <<<N0/HB, 256>>>(z0, nHc);                        /* launch 3 */

    int totH = N0 * nHc;
    int totL = N0 * nLc;
    int gridHx = (nHc > 0) ? (totH + 127) / 128 : 0;
    int gridLx = (nLc > 0) ? (totL + 127) / 128 : 0;
    if (gridHx + gridLx > 0) {
        dim3 gg(gridLx + gridHx, 2);
        k_g1 <<<gg, 128, DYNSM>>>(b1, nHc, nLc, totH, totL, gridLx);  /* launch 4 <- ncu */
    }
    k_fold  <<<1, 256>>>(W2, b2, g1, bb1);                    /* launch 5 */
    k_gemm2 <<<NPIX/128, 128, DYNSM>>>(out);                  /* launch 6 */
    k_final <<<18000, 256>>>(out, g2, bb2);                   /* launch 7 */
}

// round 16
// speedup vs baseline: 1.1911x; 1.1911x over previous
#include <cuda_runtime.h>
#include <math.h>

#define D     256
#define N0    1500
#define N1    1200
#define CATC  600
#define W96   96
#define NPIX  (N0*W96)      /* 144000 */
#define HID   256
#define H2    128
#define SPAD  36
#define SZB   (128*SPAD)
#define DYNSM (4*SZB*4)     /* 2 bufs x (A+B) = 73728 B */

/* ---------------- device scratch ----------------------------------------- */
__device__ float    g_s0[D];
__device__ float    g_accP[90][D];
__device__ float    g_t[W96];
__device__ float    g_hs[W96];
__device__ float    g_hp[W96+1];
__device__ float    g_meanH;
__device__ float    g_W1t[512*256];     /* W1 [k][o] fp32 (u-gemm)          */
__device__ unsigned g_W1tf[256*512];    /* W1 [o][k] tf32 bits              */
__device__ float    g_x [N0*D];
__device__ float    g_m0[N0*D];
__device__ float    g_m1[N0*D];
__device__ float    g_u [N0*D];
__device__ float    g_c1[(size_t)NPIX*HID];  /* relu(conv1) [pix][o]        */
__device__ float    g_sum1[HID];
__device__ float    g_sq1[HID];
__device__ float    g_sum2[H2];
__device__ float    g_sq2[H2];
__device__ unsigned g_W2p[H2*D];        /* W2 [o][c] tf32 bits              */
__device__ float    g_al[D];
__device__ float    g_b2p[H2];

__device__ __forceinline__ float sigm(float v) { return 1.f/(1.f+expf(-v)); }
__device__ __forceinline__ unsigned f2tf(float f) {
    unsigned u; asm("cvt.rna.tf32.f32 %0, %1;" : "=r"(u) : "f"(f)); return u;
}
__device__ __forceinline__ void mma8(float c[4], unsigned a0, unsigned a1,
                                     unsigned a2, unsigned a3,
                                     unsigned b0, unsigned b1) {
    asm("mma.sync.aligned.m16n8k8.row.col.f32.tf32.tf32.f32 "
        "{%0,%1,%2,%3},{%4,%5,%6,%7},{%8,%9},{%0,%1,%2,%3};"
        : "+f"(c[0]),"+f"(c[1]),"+f"(c[2]),"+f"(c[3])
        : "r"(a0),"r"(a1),"r"(a2),"r"(a3),"r"(b0),"r"(b1));
}
__device__ __forceinline__ void cpa16(void* dst, const void* src) {
    unsigned d = (unsigned)__cvta_generic_to_shared(dst);
    asm volatile("cp.async.cg.shared.global [%0], [%1], 16;"
                 :: "r"(d), "l"(src) : "memory");
}
#define CP_COMMIT() asm volatile("cp.async.commit_group;" ::: "memory")
#define CP_WAIT0()  asm volatile("cp.async.wait_group 0;" ::: "memory")

/* ---------------- init: W transforms + row partials ----------------------- */
__global__ void k_init(const float* __restrict__ W1, const float* __restrict__ W2,
                       const float* __restrict__ z0, const float* __restrict__ z1) {
    int b = blockIdx.x, t = threadIdx.x;
    if (b < 512) {
        float v = W1[t*512 + b];
        g_W1t [b*256 + t] = v;
        g_W1tf[t*512 + b] = f2tf(v);
        if (b < H2) g_W2p[b*256 + t] = f2tf(W2[b*256 + t]);
        if (b == 511) {
            g_sum1[t]=0.f; g_sq1[t]=0.f;
            if (t < H2) { g_sum2[t]=0.f; g_sq2[t]=0.f; }
        }
    } else {
        int r = b - 512;
        const float* src = (r < 50) ? (z0 + r*30*D) : (z1 + (r-50)*30*D);
        float acc = 0.f;
        #pragma unroll 6
        for (int i=0;i<30;i++) acc += src[i*D + t];
        g_accP[r][t] = acc;
    }
}

/* ---------------- prep: 2 blocks; sorts hm + prefix sums ------------------ */
__global__ void k_prep(const float* __restrict__ z1,
                       const float* __restrict__ w1, const float* __restrict__ w2,
                       const float* __restrict__ w3, const float* __restrict__ w4,
                       const float* __restrict__ w5,
                       const int* __restrict__ cdrH, const int* __restrict__ cdrL,
                       const int* __restrict__ notH, const int* __restrict__ notL,
                       int nHc, int nLc, int nHn, int nLn) {
    __shared__ float y0[D];
    __shared__ float accS[D];
    __shared__ float av[W96];
    __shared__ float bv[CATC];
    __shared__ float red[256];
    __shared__ float hmv[W96];
    __shared__ float hsS[W96];
    int t = threadIdx.x;
    int row = t >> 1, jp = t & 1;

    if (blockIdx.x == 0) {
        {
            float a = 0.f;
            for (int r=0;r<50;r++) a += g_accP[r][t];
            y0[t] = a * (1.f/N0);
            float hA = 0.f;
            for (int r=50;r<70;r++) hA += g_accP[r][t];
            accS[t] = hA;
        }
        __syncthreads();
        {
            float a = 0.f;
            #pragma unroll
            for (int k=0;k<5;k++) { int cc=t+k-2; if (cc>=0 && cc<D) a += w1[k]*y0[cc]; }
            g_s0[t] = sigm(a);
        }

        float sH0;
        {
            float yh0=accS[0]*(1.f/CATC), yh1=accS[1]*(1.f/CATC), yh2=accS[2]*(1.f/CATC);
            sH0 = sigm(w2[2]*yh0 + w2[3]*yh1 + w2[4]*yh2);
        }
        if (t < nHc) av[t] = z1[cdrH[t]*D] * sH0;
        for (int j=t; j<nHn; j+=256) bv[j] = z1[notH[j]*D] * sH0;
        __syncthreads();
        float msum = 0.f;
        if (row < nHc) {
            float ai = av[row];
            for (int j=jp; j<nHn; j+=2) msum += fabsf(ai - bv[j]);
        }
        msum += __shfl_down_sync(0xffffffffu, msum, 1, 2);
        red[t] = (jp==0 && row<nHc) ? msum : 0.f;
        __syncthreads();
        for (int m=128;m>0;m>>=1){ if(t<m) red[t]+=red[t+m]; __syncthreads(); }
        float s  = red[0] / ((float)nHc*(float)nHn);
        float gH = sigm(w4[2] * s);
        float myhm = gH * msum / (float)nHn;
        if (jp==0 && row < nHc) { g_t[row] = myhm; hmv[row] = myhm; }
        if (t==0) g_meanH = gH * s;
        __syncthreads();

        if (t < nHc) {
            float v = hmv[t]; int r = 0;
            for (int j=0;j<nHc;j++) { float vj = hmv[j]; r += (vj < v) || (vj == v && j < t); }
            hsS[r] = v;
        }
        __syncthreads();
        if (t < nHc) g_hs[t] = hsS[t];
        if (t == 0) {
            float run = 0.f;
            for (int j=0;j<nHc;j++) { g_hp[j] = run; run += hsS[j]; }
            g_hp[nHc] = run;
        }
    } else {
        {
            float a = 0.f;
            for (int r=70;r<90;r++) a += g_accP[r][t];
            accS[t] = a;
        }
        __syncthreads();
        float sL0;
        {
            float yl0=accS[0]*(1.f/CATC), yl1=accS[1]*(1.f/CATC), yl2=accS[2]*(1.f/CATC);
            sL0 = sigm(w3[2]*yl0 + w3[3]*yl1 + w3[4]*yl2);
        }
        if (t < nLc) av[t] = z1[(CATC+cdrL[t])*D] * sL0;
        for (int j=t; j<nLn; j+=256) bv[j] = z1[(CATC+notL[j])*D] * sL0;
        __syncthreads();
        float msum = 0.f;
        if (row < nLc) {
            float ai = av[row];
            for (int j=jp; j<nLn; j+=2) msum += fabsf(ai - bv[j]);
        }
        msum += __shfl_down_sync(0xffffffffu, msum, 1, 2);
        red[t] = (jp==0 && row<nLc) ? msum : 0.f;
        __syncthreads();
        for (int m=128;m>0;m>>=1){ if(t<m) red[t]+=red[t+m]; __syncthreads(); }
        float gL = sigm(w5[2] * red[0] / ((float)nLc*(float)nLn));
        if (jp==0 && row < nLc) g_t[nHc + row] = gL * msum / (float)nLn;
    }
}

/* ---------------- per-h vectors via sorted-prefix m0 ----------------------- */
#define HB 5
__global__ __launch_bounds__(256,2) void k_pre2(const float* __restrict__ z0, int nHc) {
    __shared__ float xsall[HB][D];
    __shared__ float hs[W96];
    __shared__ float hp[W96+1];
    const int t = threadIdx.x;
    const int hbase = blockIdx.x * HB;
    if (t < nHc)      hs[t] = g_hs[t];
    if (t <= nHc)     hp[t] = g_hp[t];
    const float s0 = g_s0[t];
    const float mh = g_meanH;
    const float inv = 1.f / (float)nHc;
    __syncthreads();
    const float Ptot = hp[nHc];
    #pragma unroll
    for (int hh=0; hh<HB; hh++) {
        int h = hbase + hh;
        float x = z0[h*D + t] * s0;
        xsall[hh][t] = x;
        g_x [h*D + t] = x;
        int lo = 0, hi = nHc;
        while (lo < hi) { int m = (lo+hi) >> 1; if (hs[m] <= x) lo = m+1; else hi = m; }
        float m0 = (x * (float)(2*lo - nHc) - 2.f*hp[lo] + Ptot) * inv;
        g_m0[h*D + t] = m0;
        g_m1[h*D + t] = x * mh;
    }
    __syncthreads();
    float u[HB];
    #pragma unroll
    for (int hh=0;hh<HB;hh++) u[hh]=0.f;
    #pragma unroll 4
    for (int c=0;c<D;c++) {
        float wv = g_W1t[(256+c)*256 + t];
        #pragma unroll
        for (int hh=0;hh<HB;hh++) u[hh] = fmaf(wv, xsall[hh][c], u[hh]);
    }
    #pragma unroll
    for (int hh=0;hh<HB;hh++) g_u[(hbase+hh)*D + t] = u[hh];
}

/* ======================================================================== */
/* Merged pipelined tf32 GEMM1 (R13 configuration).                         */
/* ======================================================================== */
__global__ __launch_bounds__(256,2) void k_g1(const float* __restrict__ b1,
                                              int nHc, int nLc,
                                              int totH, int totL, int gridLx) {
    extern __shared__ unsigned dyn[];
    unsigned* As = dyn;
    unsigned* Bs = dyn + 2*SZB;
    __shared__ int   hrow[128];
    __shared__ int   pcol[128];
    __shared__ float tcol[128];

    const int tid = threadIdx.x;
    const int wid = tid >> 5, lane = tid & 31;
    const int wm = wid >> 2, wn = wid & 3;
    const int g = lane >> 2, tig = lane & 3;
    const int ob = blockIdx.y * 128;
    const bool isL = ((int)blockIdx.x < gridLx);

    float c[4][4][4];
    #pragma unroll
    for (int i=0;i<4;i++) for (int j=0;j<4;j++) for (int k=0;k<4;k++) c[i][j][k]=0.f;
    float4 br[4];

    const int sm = tid >> 1, sk = (tid & 1) * 16;
    const int so = sm*SPAD + sk;
    const unsigned* wsrc = g_W1tf + (size_t)(ob+sm)*512 + sk;

    if (isL) {
        const int pb = blockIdx.x * 128;
        if (tid < 128) {
            int pix = pb + tid;
            if (pix >= totL) pix = totL - 1;
            int h = pix / nLc, w = pix - h*nLc;
            hrow[tid] = h*D; pcol[tid] = h*W96 + nHc + w; tcol[tid] = g_t[nHc + w];
        }
        __syncthreads();
        const int hb = hrow[sm];
        const float tv = tcol[sm];
        const float* src0 = g_m0 + hb + sk;
        const float* src1 = g_m1 + hb + sk;

        #pragma unroll
        for (int q=0;q<4;q++) cpa16(&As[so + q*4], wsrc + q*4);
        CP_COMMIT();
        #pragma unroll
        for (int q=0;q<4;q++) br[q] = *(const float4*)(src0 + q*4);
        #pragma unroll
        for (int q=0;q<4;q++) {
            uint4 o4;
            o4.x=f2tf(fabsf(br[q].x-tv)); o4.y=f2tf(fabsf(br[q].y-tv));
            o4.z=f2tf(fabsf(br[q].z-tv)); o4.w=f2tf(fabsf(br[q].w-tv));
            *(uint4*)&Bs[so + q*4] = o4;
        }
        CP_WAIT0();
        __syncthreads();

        for (int kc=0; kc<16; kc++) {
            const int cur = kc & 1, nxt = cur ^ 1;
            if (kc < 15) {
                const int kn = kc + 1;
                const float* s = (kn < 8) ? (src0 + kn*32) : (src1 + (kn-8)*32);
                #pragma unroll
                for (int q=0;q<4;q++) cpa16(&As[nxt*SZB + so + q*4], wsrc + kn*32 + q*4);
                CP_COMMIT();
                #pragma unroll
                for (int q=0;q<4;q++) br[q] = *(const float4*)(s + q*4);
            }
            const unsigned* Ab = As + cur*SZB;
            const unsigned* Bb = Bs + cur*SZB;
            #pragma unroll
            for (int ks=0; ks<4; ks++) {
                const int kk = ks*8;
                unsigned af[4][4], bf[4][2];
                #pragma unroll
                for (int mt=0;mt<4;mt++) {
                    int rb = (wm*64 + mt*16 + g)*SPAD + kk + tig;
                    af[mt][0]=Ab[rb]; af[mt][1]=Ab[rb+8*SPAD];
                    af[mt][2]=Ab[rb+4]; af[mt][3]=Ab[rb+8*SPAD+4];
                }
                #pragma unroll
                for (int nt=0;nt<4;nt++) {
                    int cb = (wn*32 + nt*8 + g)*SPAD + kk + tig;
                    bf[nt][0]=Bb[cb]; bf[nt][1]=Bb[cb+4];
                }
                #pragma unroll
                for (int mt=0;mt<4;mt++)
                    #pragma unroll
                    for (int nt=0;nt<4;nt++)
                        mma8(c[mt][nt], af[mt][0],af[mt][1],af[mt][2],af[mt][3],
                             bf[nt][0], bf[nt][1]);
            }
            if (kc < 15) {
                #pragma unroll
                for (int q=0;q<4;q++) {
                    uint4 o4;
                    o4.x=f2tf(fabsf(br[q].x-tv)); o4.y=f2tf(fabsf(br[q].y-tv));
                    o4.z=f2tf(fabsf(br[q].z-tv)); o4.w=f2tf(fabsf(br[q].w-tv));
                    *(uint4*)&Bs[nxt*SZB + so + q*4] = o4;
                }
                CP_WAIT0();
            }
            __syncthreads();
        }

        #pragma unroll
        for (int mt=0;mt<4;mt++) {
            #pragma unroll
            for (int half=0; half<2; half++) {
                int o = ob + wm*64 + mt*16 + g + half*8;
                float bias = b1[o];
                float s = 0.f, q = 0.f;
                #pragma unroll
                for (int nt=0;nt<4;nt++) {
                    #pragma unroll
                    for (int cc=0;cc<2;cc++) {
                        int n = wn*32 + nt*8 + tig*2 + cc;
                        float r = fmaxf(c[mt][nt][half*2+cc] + bias, 0.f);
                        if (pb + n < totL) {
                            g_c1[(size_t)pcol[n]*256 + o] = r;
                            s += r; q += r*r;
                        }
                    }
                }
                s += __shfl_down_sync(0xffffffffu, s, 2, 4);
                s += __shfl_down_sync(0xffffffffu, s, 1, 4);
                q += __shfl_down_sync(0xffffffffu, q, 2, 4);
                q += __shfl_down_sync(0xffffffffu, q, 1, 4);
                if (tig == 0) { atomicAdd(&g_sum1[o], s); atomicAdd(&g_sq1[o], q); }
            }
        }
    } else {
        const int pb = (blockIdx.x - gridLx) * 128;
        if (tid < 128) {
            int pix = pb + tid;
            if (pix >= totH) pix = totH - 1;
            int h = pix / nHc, w = pix - h*nHc;
            hrow[tid] = h*D; pcol[tid] = h*W96 + w; tcol[tid] = g_t[w];
        }
        __syncthreads();
        const int hb = hrow[sm];
        const float tv = tcol[sm];
        const float* xsrc = g_x + hb + sk;

        #pragma unroll
        for (int q=0;q<4;q++) cpa16(&As[so + q*4], wsrc + q*4);
        CP_COMMIT();
        #pragma unroll
        for (int q=0;q<4;q++) br[q] = *(const float4*)(xsrc + q*4);
        #pragma unroll
        for (int q=0;q<4;q++) {
            uint4 o4;
            o4.x=f2tf(fabsf(br[q].x-tv)); o4.y=f2tf(fabsf(br[q].y-tv));
            o4.z=f2tf(fabsf(br[q].z-tv)); o4.w=f2tf(fabsf(br[q].w-tv));
            *(uint4*)&Bs[so + q*4] = o4;
        }
        CP_WAIT0();
        __syncthreads();

        for (int kc=0; kc<8; kc++) {
            const int cur = kc & 1, nxt = cur ^ 1;
            if (kc < 7) {
                #pragma unroll
                for (int q=0;q<4;q++) cpa16(&As[nxt*SZB + so + q*4], wsrc + (kc+1)*32 + q*4);
                CP_COMMIT();
                #pragma unroll
                for (int q=0;q<4;q++) br[q] = *(const float4*)(xsrc + (kc+1)*32 + q*4);
            }
            const unsigned* Ab = As + cur*SZB;
            const unsigned* Bb = Bs + cur*SZB;
            #pragma unroll
            for (int ks=0; ks<4; ks++) {
                const int kk = ks*8;
                unsigned af[4][4], bf[4][2];
                #pragma unroll
                for (int mt=0;mt<4;mt++) {
                    int rb = (wm*64 + mt*16 + g)*SPAD + kk + tig;
                    af[mt][0]=Ab[rb]; af[mt][1]=Ab[rb+8*SPAD];
                    af[mt][2]=Ab[rb+4]; af[mt][3]=Ab[rb+8*SPAD+4];
                }
                #pragma unroll
                for (int nt=0;nt<4;nt++) {
                    int cb = (wn*32 + nt*8 + g)*SPAD + kk + tig;
                    bf[nt][0]=Bb[cb]; bf[nt][1]=Bb[cb+4];
                }
                #pragma unroll
                for (int mt=0;mt<4;mt++)
                    #pragma unroll
                    for (int nt=0;nt<4;nt++)
                        mma8(c[mt][nt], af[mt][0],af[mt][1],af[mt][2],af[mt][3],
                             bf[nt][0], bf[nt][1]);
            }
            if (kc < 7) {
                #pragma unroll
                for (int q=0;q<4;q++) {
                    uint4 o4;
                    o4.x=f2tf(fabsf(br[q].x-tv)); o4.y=f2tf(fabsf(br[q].y-tv));
                    o4.z=f2tf(fabsf(br[q].z-tv)); o4.w=f2tf(fabsf(br[q].w-tv));
                    *(uint4*)&Bs[nxt*SZB + so + q*4] = o4;
                }
                CP_WAIT0();
            }
            __syncthreads();
        }

        #pragma unroll
        for (int mt=0;mt<4;mt++) {
            #pragma unroll
            for (int half=0; half<2; half++) {
                int o = ob + wm*64 + mt*16 + g + half*8;
                float bias = b1[o];
                float s = 0.f, q = 0.f;
                #pragma unroll
                for (int nt=0;nt<4;nt++) {
                    #pragma unroll
                    for (int cc=0;cc<2;cc++) {
                        int n = wn*32 + nt*8 + tig*2 + cc;
                        float r = c[mt][nt][half*2+cc]
                                + g_u[hrow[n] + o] * tcol[n] + bias;
                        r = fmaxf(r, 0.f);
                        if (pb + n < totH) {
                            g_c1[(size_t)pcol[n]*256 + o] = r;
                            s += r; q += r*r;
                        }
                    }
                }
                s += __shfl_down_sync(0xffffffffu, s, 2, 4);
                s += __shfl_down_sync(0xffffffffu, s, 1, 4);
                q += __shfl_down_sync(0xffffffffu, q, 2, 4);
                q += __shfl_down_sync(0xffffffffu, q, 1, 4);
                if (tig == 0) { atomicAdd(&g_sum1[o], s); atomicAdd(&g_sq1[o], q); }
            }
        }
    }
}

/* ---------------- fold: BN1 alpha/beta + warp-parallel b2p ----------------- */
__global__ void k_fold(const float* __restrict__ W2, const float* __restrict__ b2,
                       const float* __restrict__ g1, const float* __restrict__ bb1) {
    __shared__ float be[D];
    int t = threadIdx.x;
    int w = t >> 5, lane = t & 31;
    float mean = g_sum1[t] * (1.f/NPIX);
    float var  = g_sq1[t]  * (1.f/NPIX) - mean*mean;
    float a    = g1[t] * rsqrtf(var + 1e-5f);
    g_al[t] = a;
    be[t] = bb1[t] - mean*a;
    __syncthreads();
    /* b2p: 8 warps x 16 o's each, lane-strided dot + shfl reduce */
    #pragma unroll
    for (int oi=0; oi<16; oi++) {
        int o = w*16 + oi;
        float s = 0.f;
        #pragma unroll
        for (int c=lane; c<D; c+=32) s += W2[o*D + c] * be[c];
        #pragma unroll
        for (int off=16; off; off>>=1) s += __shfl_down_sync(0xffffffffu, s, off);
        if (lane == 0) g_b2p[o] = s + b2[o];
    }
}

/* ======================================================================== */
/* Pipelined tf32 GEMM2 (R13 configuration). alpha applied in B-convert.    */
/* ======================================================================== */
__global__ __launch_bounds__(256,2) void k_gemm2(float* __restrict__ out) {
    extern __shared__ unsigned dyn[];
    unsigned* As = dyn;
    unsigned* Bs = dyn + 2*SZB;
    __shared__ float alS[D];

    const int tid = threadIdx.x;
    const int wid = tid >> 5, lane = tid & 31;
    const int wm = wid >> 2, wn = wid & 3;
    const int g = lane >> 2, tig = lane & 3;
    const int pb = blockIdx.x * 128;

    const int sm = tid >> 1, sk = (tid & 1) * 16;
    const int so = sm*SPAD + sk;
    const unsigned* wsrc = g_W2p + sm*256 + sk;
    const float*    bsrc = g_c1 + (size_t)(pb+sm)*256 + sk;

    alS[tid] = g_al[tid];
    __syncthreads();

    float c[4][4][4];
    #pragma unroll
    for (int i=0;i<4;i++) for (int j=0;j<4;j++) for (int k=0;k<4;k++) c[i][j][k]=0.f;
    float4 br[4];

    #pragma unroll
    for (int q=0;q<4;q++) cpa16(&As[so + q*4], wsrc + q*4);
    CP_COMMIT();
    #pragma unroll
    for (int q=0;q<4;q++) br[q] = *(const float4*)(bsrc + q*4);
    #pragma unroll
    for (int q=0;q<4;q++) {
        int ch = sk + q*4;
        uint4 o4;
        o4.x=f2tf(br[q].x*alS[ch]);   o4.y=f2tf(br[q].y*alS[ch+1]);
        o4.z=f2tf(br[q].z*alS[ch+2]); o4.w=f2tf(br[q].w*alS[ch+3]);
        *(uint4*)&Bs[so + q*4] = o4;
    }
    CP_WAIT0();
    __syncthreads();

    for (int kc=0; kc<8; kc++) {
        const int cur = kc & 1, nxt = cur ^ 1;
        if (kc < 7) {
            #pragma unroll
            for (int q=0;q<4;q++) cpa16(&As[nxt*SZB + so + q*4], wsrc + (kc+1)*32 + q*4);
            CP_COMMIT();
            #pragma unroll
            for (int q=0;q<4;q++) br[q] = *(const float4*)(bsrc + (kc+1)*32 + q*4);
        }
        const unsigned* Ab = As + cur*SZB;
        const unsigned* Bb = Bs + cur*SZB;
        #pragma unroll
        for (int ks=0; ks<4; ks++) {
            const int kk = ks*8;
            unsigned af[4][4], bf[4][2];
            #pragma unroll
            for (int mt=0;mt<4;mt++) {
                int rb = (wm*64 + mt*16 + g)*SPAD + kk + tig;
                af[mt][0]=Ab[rb]; af[mt][1]=Ab[rb+8*SPAD];
                af[mt][2]=Ab[rb+4]; af[mt][3]=Ab[rb+8*SPAD+4];
            }
            #pragma unroll
            for (int nt=0;nt<4;nt++) {
                int cb = (wn*32 + nt*8 + g)*SPAD + kk + tig;
                bf[nt][0]=Bb[cb]; bf[nt][1]=Bb[cb+4];
            }
            #pragma unroll
            for (int mt=0;mt<4;mt++)
                #pragma unroll
                for (int nt=0;nt<4;nt++)
                    mma8(c[mt][nt], af[mt][0],af[mt][1],af[mt][2],af[mt][3],
                         bf[nt][0], bf[nt][1]);
        }
        if (kc < 7) {
            #pragma unroll
            for (int q=0;q<4;q++) {
                int ch = (kc+1)*32 + sk + q*4;
                uint4 o4;
                o4.x=f2tf(br[q].x*alS[ch]);   o4.y=f2tf(br[q].y*alS[ch+1]);
                o4.z=f2tf(br[q].z*alS[ch+2]); o4.w=f2tf(br[q].w*alS[ch+3]);
                *(uint4*)&Bs[nxt*SZB + so + q*4] = o4;
            }
            CP_WAIT0();
        }
        __syncthreads();
    }

    #pragma unroll
    for (int mt=0;mt<4;mt++) {
        #pragma unroll
        for (int half=0; half<2; half++) {
            int o = wm*64 + mt*16 + g + half*8;
            float bias = g_b2p[o];
            float s = 0.f, q = 0.f;
            #pragma unroll
            for (int nt=0;nt<4;nt++) {
                int n = pb + wn*32 + nt*8 + tig*2;
                float r0 = fmaxf(c[mt][nt][half*2+0] + bias, 0.f);
                float r1 = fmaxf(c[mt][nt][half*2+1] + bias, 0.f);
                *(float2*)&out[(size_t)o*NPIX + n] = make_float2(r0, r1);
                s += r0 + r1; q += r0*r0 + r1*r1;
            }
            s += __shfl_down_sync(0xffffffffu, s, 2, 4);
            s += __shfl_down_sync(0xffffffffu, s, 1, 4);
            q += __shfl_down_sync(0xffffffffu, q, 2, 4);
            q += __shfl_down_sync(0xffffffffu, q, 1, 4);
            if (tig == 0) { atomicAdd(&g_sum2[o], s); atomicAdd(&g_sq2[o], q); }
        }
    }
}

/* ---------------- final BN2 affine in place (a2/be2 inline) ---------------- */
__global__ void k_final(float* __restrict__ out,
                        const float* __restrict__ g2, const float* __restrict__ bb2) {
    size_t idx = (size_t)blockIdx.x*256 + threadIdx.x;
    size_t i4  = idx * 4;
    int c = (int)(i4 / NPIX);
    float mean = g_sum2[c]*(1.f/NPIX);
    float var  = g_sq2[c]*(1.f/NPIX) - mean*mean;
    float a    = g2[c]*rsqrtf(var + 1e-5f);
    float b    = bb2[c] - mean*a;
    float4 v = *(float4*)(out + i4);
    v.x = fmaf(a, v.x, b); v.y = fmaf(a, v.y, b);
    v.z = fmaf(a, v.z, b); v.w = fmaf(a, v.w, b);
    *(float4*)(out + i4) = v;
}

/* ---------------- launch -------------------------------------------------- */
extern "C" void kernel_launch(void* const* d_in, const int* in_sizes, int n_in,
                              void* d_out, int out_size) {
    const float* z0  = (const float*)d_in[0];
    const float* z1  = (const float*)d_in[1];
    const float* w1  = (const float*)d_in[2];
    const float* w2  = (const float*)d_in[3];
    const float* w3  = (const float*)d_in[4];
    const float* w4  = (const float*)d_in[5];
    const float* w5  = (const float*)d_in[6];
    const float* W1  = (const float*)d_in[7];
    const float* b1  = (const float*)d_in[8];
    const float* g1  = (const float*)d_in[9];
    const float* bb1 = (const float*)d_in[10];
    const float* W2  = (const float*)d_in[11];
    const float* b2  = (const float*)d_in[12];
    const float* g2  = (const float*)d_in[13];
    const float* bb2 = (const float*)d_in[14];
    const int* cdrH = (const int*)d_in[16];
    const int* cdrL = (const int*)d_in[17];
    const int* notH = (const int*)d_in[18];
    const int* notL = (const int*)d_in[19];
    int nHc = in_sizes[16], nLc = in_sizes[17];
    int nHn = in_sizes[18], nLn = in_sizes[19];
    float* out = (float*)d_out;

    cudaFuncSetAttribute(k_g1,    cudaFuncAttributeMaxDynamicSharedMemorySize, DYNSM);
    cudaFuncSetAttribute(k_gemm2, cudaFuncAttributeMaxDynamicSharedMemorySize, DYNSM);

    k_init  <<<602, 256>>>(W1, W2, z0, z1);                   /* launch 1 */
    k_prep  <<<2, 256>>>(z1, w1, w2, w3, w4, w5, cdrH, cdrL, notH, notL,
                         nHc, nLc, nHn, nLn);                 /* launch 2 */
    k_pre2  <<<N0/HB, 256>>>(z0, nHc);                        /* launch 3 */

    int totH = N0 * nHc;
    int totL = N0 * nLc;
    int gridHx = (nHc > 0) ? (totH + 127) / 128 : 0;
    int gridLx = (nLc > 0) ? (totL + 127) / 128 : 0;
    if (gridHx + gridLx > 0) {
        dim3 gg(gridLx + gridHx, 2);
        k_g1 <<<gg, 256, DYNSM>>>(b1, nHc, nLc, totH, totL, gridLx);  /* launch 4 <- ncu */
    }
    k_fold  <<<1, 256>>>(W2, b2, g1, bb1);                    /* launch 5 */
    k_gemm2 <<<NPIX/128, 256, DYNSM>>>(out);                  /* launch 6 */
    k_final <<<18000, 256>>>(out, g2, bb2);                   /* launch 7 */
}